// round 14
// baseline (speedup 1.0000x reference)
#include <cuda_runtime.h>

// Fused local NCC loss (kernel=3, zero 'same' padding) over 192^3 f32 volumes.
// One warp spans the full d=192: lane owns d={2l, 64+2l, 128+2l} as f32x2
// packs (coalesced LDG.64). H=1 row per warp; rows h-1,h,h+1 via per-row
// pointers (zero-buffer redirect at h edges). w marched with a 2-plane
// T-scheme ring built in place; all 18 plane loads batched per build.
// d-window seams via publish-SEL + index-shfl; packed f32x2 NCC epilogue.
// 8 warps per block over adjacent h rows: row redundancy 1.25x per block,
// interior halo rows are sibling warps' center rows -> L1-warm.

#define SZ    192
#define SZ2   (SZ * SZ)
#define NTOT  (SZ * SZ * SZ)
#define WCHUNK 16
#define BY     8               // warps (h rows) per block
#define GY     24              // 192 / BY
#define GZ     12              // 192 / WCHUNK
#define NBLK   (GY * GZ)       // 288 (one wave at 2 blocks/SM: 296 slots)

typedef unsigned long long u64;

__device__ float        g_zero[4608];          // static zero (BSS) pad source
__device__ float        g_partial[NBLK];
__device__ unsigned int g_count = 0;

__device__ __forceinline__ u64 pk2(float lo, float hi) {
    u64 r; asm("mov.b64 %0, {%1, %2};" : "=l"(r) : "f"(lo), "f"(hi)); return r;
}
__device__ __forceinline__ void upk2(u64 v, float& lo, float& hi) {
    asm("mov.b64 {%0, %1}, %2;" : "=f"(lo), "=f"(hi) : "l"(v));
}
__device__ __forceinline__ u64 add2(u64 a, u64 b) {
    u64 r; asm("add.rn.f32x2 %0, %1, %2;" : "=l"(r) : "l"(a), "l"(b)); return r;
}
__device__ __forceinline__ u64 mul2(u64 a, u64 b) {
    u64 r; asm("mul.rn.f32x2 %0, %1, %2;" : "=l"(r) : "l"(a), "l"(b)); return r;
}
__device__ __forceinline__ u64 fma2(u64 a, u64 b, u64 c) {
    u64 r; asm("fma.rn.f32x2 %0, %1, %2, %3;" : "=l"(r) : "l"(a), "l"(b), "l"(c)); return r;
}

struct PS { u64 v[5][3]; };   // components {I,J,II,JJ,IJ} x packs {s=0,1,2}

// Build plane sums over the 3 h-rows. foff = float offset of this plane
// relative to the (already w-positioned) row pointers.
__device__ __forceinline__ void build_plane(
    PS& C, const float* const (&pI)[3], const float* const (&pJ)[3],
    int foff, int wp)
{
    if ((unsigned)wp >= (unsigned)SZ) {
        #pragma unroll
        for (int c = 0; c < 5; c++)
            #pragma unroll
            for (int s = 0; s < 3; s++) C.v[c][s] = 0ull;
        return;
    }
    #pragma unroll
    for (int s = 0; s < 3; s++) {
        u64 aI, aJ, aII, aJJ, aIJ;
        #pragma unroll
        for (int r = 0; r < 3; r++) {
            u64 I = *(const u64*)(pI[r] + foff + 64 * s);
            u64 J = *(const u64*)(pJ[r] + foff + 64 * s);
            if (r == 0) {
                aI = I; aJ = J;
                aII = mul2(I, I); aJJ = mul2(J, J); aIJ = mul2(I, J);
            } else {
                aI = add2(aI, I); aJ = add2(aJ, J);
                aII = fma2(I, I, aII); aJJ = fma2(J, J, aJJ); aIJ = fma2(I, J, aIJ);
            }
        }
        C.v[0][s] = aI; C.v[1][s] = aJ; C.v[2][s] = aII; C.v[3][s] = aJJ; C.v[4][s] = aIJ;
    }
}

// Emit one output w-plane: window sums = T + Cr; also updates T = Bo + Cr.
__device__ __forceinline__ float emit(PS& T, const PS& Bo, const PS& Cr,
                                      int lane, u64 ninv2, u64 eps2)
{
    u64 o[5][3];   // per component: packed (out[2s], out[2s+1])
    #pragma unroll
    for (int c = 0; c < 5; c++) {
        float lo[3], hi[3];
        #pragma unroll
        for (int s = 0; s < 3; s++) {
            u64 Pw = add2(T.v[c][s], Cr.v[c][s]);
            T.v[c][s] = add2(Bo.v[c][s], Cr.v[c][s]);
            upk2(Pw, lo[s], hi[s]);
        }
        #pragma unroll
        for (int s = 0; s < 3; s++) {
            // prev = elem(d0-1): lane l-1's hi[s]; lane0 <- lane31's hi[s-1] (0 if s==0)
            float pubp = (lane == 31) ? (s ? hi[s - 1] : 0.f) : hi[s];
            float prev = __shfl_sync(0xffffffffu, pubp, (lane + 31) & 31);
            // next = elem(d1+1): lane l+1's lo[s]; lane31 <- lane0's lo[s+1] (0 if s==2)
            float pubn = (lane == 0) ? (s < 2 ? lo[s + 1] : 0.f) : lo[s];
            float next = __shfl_sync(0xffffffffu, pubn, (lane + 1) & 31);
            float t = lo[s] + hi[s];
            o[c][s] = add2(pk2(t, t), pk2(prev, next));
        }
    }
    float acc = 0.f;
    #pragma unroll
    for (int s = 0; s < 3; s++) {
        u64 sI = o[0][s], sJ = o[1][s];
        u64 m1n = mul2(sI, ninv2);
        u64 m2n = mul2(sJ, ninv2);
        u64 cross = fma2(m2n, sI, o[4][s]);   // sum((I-uI)(J-uJ))
        u64 Iv    = fma2(m1n, sI, o[2][s]);   // sum((I-uI)^2)
        u64 Jv    = fma2(m2n, sJ, o[3][s]);   // sum((J-uJ)^2)
        u64 den   = fma2(Iv, Jv, eps2);
        u64 num   = mul2(cross, cross);
        float n0, n1, d0, d1;
        upk2(num, n0, n1);
        upk2(den, d0, d1);
        acc += __fdividef(n0, d0) + __fdividef(n1, d1);
    }
    return acc;
}

__global__ __launch_bounds__(32 * BY, 2)
void lncc_fused_kernel(const float* __restrict__ pred,
                       const float* __restrict__ targ,
                       float* __restrict__ out)
{
    const int lane = threadIdx.x;                   // 0..31
    const int h    = blockIdx.y * BY + threadIdx.y; // one h row per warp
    const int w0   = blockIdx.z * WCHUNK;

    const u64 ninv2 = pk2(-1.0f / 27.0f, -1.0f / 27.0f);
    const u64 eps2  = pk2(1e-5f, 1e-5f);

    // Per-row pointers (w-positioned at plane w0-1, lane-offset applied);
    // out-of-range h rows redirect into the static zero buffer.
    const float* pI[3];
    const float* pJ[3];
    #pragma unroll
    for (int r = 0; r < 3; r++) {
        int hh = h - 1 + r;
        bool ok = (hh >= 0) && (hh < SZ);
        long off = (long)hh * SZ2 + (long)(w0 - 1) * SZ + 2 * lane;
        pI[r] = ok ? pred + off : g_zero + 2 * lane;
        pJ[r] = ok ? targ + off : g_zero + 2 * lane;
    }

    PS T, B0, B1;
    int wp = w0 - 1;
    build_plane(B0, pI, pJ, 0,  wp);        // plane k=0
    build_plane(B1, pI, pJ, SZ, wp + 1);    // plane k=1
    #pragma unroll
    for (int c = 0; c < 5; c++)
        #pragma unroll
        for (int s = 0; s < 3; s++)
            T.v[c][s] = add2(B0.v[c][s], B1.v[c][s]);
    #pragma unroll
    for (int r = 0; r < 3; r++) { pI[r] += 2 * SZ; pJ[r] += 2 * SZ; }
    wp += 2;

    float acc = 0.f;
    // planes k=2..17 (16 emits), C alternates into B0/B1 (in-place ring)
    for (int t = 0; t < WCHUNK / 2; t++) {
        build_plane(B0, pI, pJ, 0, wp);        // even plane: Cr=B0, Bo=B1
        acc += emit(T, B1, B0, lane, ninv2, eps2);
        build_plane(B1, pI, pJ, SZ, wp + 1);   // odd plane:  Cr=B1, Bo=B0
        acc += emit(T, B0, B1, lane, ninv2, eps2);
        #pragma unroll
        for (int r = 0; r < 3; r++) { pI[r] += 2 * SZ; pJ[r] += 2 * SZ; }
        wp += 2;
    }

    // ---- deterministic in-kernel reduction ----
    __shared__ float  sred[32 * BY];
    __shared__ double dred[32 * BY];
    __shared__ unsigned int s_last;
    const int tid = threadIdx.y * 32 + lane;

    sred[tid] = acc;
    __syncthreads();
    #pragma unroll
    for (int s = 16 * BY; s > 0; s >>= 1) {
        if (tid < s) sred[tid] += sred[tid + s];
        __syncthreads();
    }
    if (tid == 0) {
        const int blin = blockIdx.y + GY * blockIdx.z;
        g_partial[blin] = sred[0];
        __threadfence();
        unsigned old = atomicAdd(&g_count, 1u);
        s_last = (old == (unsigned)(NBLK - 1)) ? 1u : 0u;
    }
    __syncthreads();

    if (s_last) {
        double v = 0.0;
        for (int i = tid; i < NBLK; i += 32 * BY)
            v += (double)g_partial[i];
        dred[tid] = v;
        __syncthreads();
        #pragma unroll
        for (int k = 16 * BY; k > 0; k >>= 1) {
            if (tid < k) dred[tid] += dred[tid + k];
            __syncthreads();
        }
        if (tid == 0) {
            out[0] = (float)(-dred[0] / (double)NTOT);
            g_count = 0;   // reset for the next (graph-replayed) call
        }
    }
}

extern "C" void kernel_launch(void* const* d_in, const int* in_sizes, int n_in,
                              void* d_out, int out_size) {
    const float* pred = (const float*)d_in[0];
    const float* targ = (const float*)d_in[1];
    dim3 grid(1, GY, GZ);
    dim3 block(32, BY, 1);
    lncc_fused_kernel<<<grid, block>>>(pred, targ, (float*)d_out);
}